// round 2
// baseline (speedup 1.0000x reference)
#include <cuda_runtime.h>
#include <cuda_bf16.h>
#include <cstdint>

// ---------------------------------------------------------------------------
// LocalBitPredictor: per-pixel 2-layer MLP over 71 binary 3x3-neighborhood
// bits of an 8-channel binary image.
//   feat(63 live bits) @ W1 + b1 -> relu -> @ W2(32x8) + b2
// Layer 1: bf16 mma.sync m16n8k16, K=64 (63 features + bias lane), weights
//   split hi+lo bf16 (exact: features are {0,1}).
// Layer 2: accumulator fragments re-used directly as A fragments of a second
//   m16n8k16 (K=32 hidden), relu + hi/lo split in registers.
// ---------------------------------------------------------------------------

#define ZROW 264     // packed z row stride (256 + halo + pad)
#define BSTRIDE 136  // B smem row stride in bytes (64 bf16 = 128B + 8 pad)
#define W2STRIDE 72  // W2 smem row stride (32 bf16 = 64B + 8 pad)

static __device__ __forceinline__ void mma16816(float* c, const uint32_t* a,
                                                const uint32_t* b) {
  asm volatile(
      "mma.sync.aligned.m16n8k16.row.col.f32.bf16.bf16.f32 "
      "{%0,%1,%2,%3}, {%4,%5,%6,%7}, {%8,%9}, {%0,%1,%2,%3};"
      : "+f"(c[0]), "+f"(c[1]), "+f"(c[2]), "+f"(c[3])
      : "r"(a[0]), "r"(a[1]), "r"(a[2]), "r"(a[3]), "r"(b[0]), "r"(b[1]));
}

static __device__ __forceinline__ uint32_t pack_bf16(float lo, float hi) {
  uint32_t r;
  asm("cvt.rn.bf16x2.f32 %0, %1, %2;" : "=r"(r) : "f"(hi), "f"(lo));
  return r;
}

// residual (lo part) of an f32 pair vs its packed-bf16 rounding, re-packed
static __device__ __forceinline__ uint32_t resid_pack(uint32_t h, float lo,
                                                      float hi) {
  float hlo = __uint_as_float(h << 16);
  float hhi = __uint_as_float(h & 0xFFFF0000u);
  return pack_bf16(lo - hlo, hi - hhi);
}

__global__ void __launch_bounds__(256)
lbp_kernel(const float* __restrict__ z, const float* __restrict__ W1,
           const float* __restrict__ b1, const float* __restrict__ W2,
           const float* __restrict__ b2, float* __restrict__ out) {
  __shared__ unsigned char Zs[10 * ZROW];
  __shared__ unsigned char Bh[32 * BSTRIDE];
  __shared__ unsigned char Bl[32 * BSTRIDE];
  __shared__ unsigned char W2hs[8 * W2STRIDE];
  __shared__ unsigned char W2ls[8 * W2STRIDE];
  __shared__ float b2s[8];

  const int tid = threadIdx.x;
  const int bb = blockIdx.y;      // batch
  const int y0 = blockIdx.x * 8;  // row-strip base

  // ---- pack z into channel-bit bytes: rows y0-1..y0+8, halo cols zeroed ---
  {
    const int x = tid;  // 256 threads == 256 columns
#pragma unroll
    for (int r = 0; r < 10; ++r) {
      int y = y0 + r - 1;
      unsigned v = 0;
      if (y >= 0 && y < 256) {
        const float* zp = z + (size_t)bb * 8 * 65536 + (size_t)y * 256 + x;
#pragma unroll
        for (int c = 0; c < 8; ++c)
          v |= (zp[(size_t)c * 65536] > 0.5f ? 1u : 0u) << c;
      }
      Zs[r * ZROW + x + 1] = (unsigned char)v;
    }
    if (tid < 10) {
      Zs[tid * ZROW + 0] = 0;
      Zs[tid * ZROW + 257] = 0;
    }
  }

  // ---- build layer-1 B tiles: [n][kf] K-major, hi/lo bf16 split -----------
  // kf = c*8 + pidx; p = pidx<4 ? pidx : pidx+1 (center masked).
  // kf==63 is the bias lane (A supplies constant 1.0 there).
  for (int i = tid; i < 2048; i += 256) {
    int n = i & 31, kf = i >> 5;
    float w;
    if (kf == 63) {
      w = b1[n];
    } else {
      int c = kf >> 3, pi = kf & 7;
      int p = pi < 4 ? pi : pi + 1;
      w = W1[(c * 9 + p) * 32 + n];
    }
    __nv_bfloat16 hi = __float2bfloat16(w);
    float hif = __bfloat162float(hi);
    __nv_bfloat16 lo = __float2bfloat16(w - hif);
    *reinterpret_cast<__nv_bfloat16*>(Bh + n * BSTRIDE + kf * 2) = hi;
    *reinterpret_cast<__nv_bfloat16*>(Bl + n * BSTRIDE + kf * 2) = lo;
  }
  // ---- W2 as [n'][d], hi/lo split; b2 ------------------------------------
  {
    int d = tid >> 3, n = tid & 7;  // tid < 256 covers 32x8
    float w = W2[d * 8 + n];
    __nv_bfloat16 hi = __float2bfloat16(w);
    float hif = __bfloat162float(hi);
    __nv_bfloat16 lo = __float2bfloat16(w - hif);
    *reinterpret_cast<__nv_bfloat16*>(W2hs + n * W2STRIDE + d * 2) = hi;
    *reinterpret_cast<__nv_bfloat16*>(W2ls + n * W2STRIDE + d * 2) = lo;
    if (tid < 8) b2s[tid] = b2[tid];
  }
  __syncthreads();

  const int lane = tid & 31;
  const int warp = tid >> 5;
  const int lq = lane & 3;   // quad index (k-col group / output-n group)
  const int lr = lane >> 2;  // row-in-fragment group

  // ---- hoist B fragments into registers -----------------------------------
  uint32_t bhf[4][4][2], blf[4][4][2];
#pragma unroll
  for (int ks = 0; ks < 4; ++ks)
#pragma unroll
    for (int nt = 0; nt < 4; ++nt) {
      const uint32_t* p = reinterpret_cast<const uint32_t*>(
          Bh + (nt * 8 + lr) * BSTRIDE + (ks * 16 + lq * 2) * 2);
      const uint32_t* q = reinterpret_cast<const uint32_t*>(
          Bl + (nt * 8 + lr) * BSTRIDE + (ks * 16 + lq * 2) * 2);
      bhf[ks][nt][0] = p[0];
      bhf[ks][nt][1] = p[4];  // +8 bf16 = +16B
      blf[ks][nt][0] = q[0];
      blf[ks][nt][1] = q[4];
    }
  uint32_t w2hf[2][2], w2lf[2][2];
#pragma unroll
  for (int ks = 0; ks < 2; ++ks) {
    const uint32_t* p = reinterpret_cast<const uint32_t*>(
        W2hs + lr * W2STRIDE + (ks * 16 + lq * 2) * 2);
    const uint32_t* q = reinterpret_cast<const uint32_t*>(
        W2ls + lr * W2STRIDE + (ks * 16 + lq * 2) * 2);
    w2hf[ks][0] = p[0];
    w2hf[ks][1] = p[4];
    w2lf[ks][0] = q[0];
    w2lf[ks][1] = q[4];
  }
  const float bq0 = b2s[lq * 2], bq1 = b2s[lq * 2 + 1];

  // neighbor-position pairs per quad: pidx pairs (0,1),(2,3),(4,5),(6,7)
  // -> p pairs (0,1),(2,3),(5,6),(7,8)   [p: 3x3 position, center p=4 skipped]
  const int pA_tab[4] = {0, 2, 5, 7};
  const int pB_tab[4] = {1, 3, 6, 8};
  const int pA = pA_tab[lq], pB = pB_tab[lq];
  const int oA = (pA / 3) * ZROW + (pA % 3);  // offset of (dy,dx) rel. to
  const int oB = (pB / 3) * ZROW + (pB % 3);  // Zs[row*ZROW + x] (x already +0)

  // ---- main loop: each warp does 16 tiles of 16 pixels --------------------
  for (int ti = warp; ti < 128; ti += 8) {
    const int row = ti >> 4;         // 0..7 within strip
    const int xb = (ti & 15) * 16;   // tile x base
    const int y = y0 + row;
    const int x1 = xb + lr, x2 = x1 + 8;

    // Zs[(row+dy+1)*ZROW + (x+dx) + 1]; base at (row)*ZROW + x covers dy=-1
    const unsigned char* zb1 = Zs + row * ZROW + x1;
    const unsigned char* zb2 = Zs + row * ZROW + x2;
    unsigned vA1 = zb1[oA], vB1 = zb1[oB];
    unsigned vA2 = zb2[oA], vB2 = zb2[oB];

    // A fragments: A[k] = {px1 c0-pair, px2 c0-pair, px1 c1-pair, px2 c1-pair}
    uint32_t A[4][4];
#pragma unroll
    for (int k = 0; k < 4; ++k) {
      unsigned sA1 = vA1 >> (2 * k), sB1 = vB1 >> (2 * k);
      unsigned sA2 = vA2 >> (2 * k), sB2 = vB2 >> (2 * k);
      A[k][0] = (sA1 & 1) * 0x3F80u + (sB1 & 1) * 0x3F800000u;
      A[k][1] = (sA2 & 1) * 0x3F80u + (sB2 & 1) * 0x3F800000u;
      A[k][2] = ((sA1 >> 1) & 1) * 0x3F80u + ((sB1 >> 1) & 1) * 0x3F800000u;
      A[k][3] = ((sA2 >> 1) & 1) * 0x3F80u + ((sB2 >> 1) & 1) * 0x3F800000u;
    }
    if (lq == 3) {  // kf=63 bias lane: force A = 1.0 (upper half, kstep 3)
      A[3][2] = (A[3][2] & 0xFFFFu) | 0x3F800000u;
      A[3][3] = (A[3][3] & 0xFFFFu) | 0x3F800000u;
    }

    // ---- layer 1: h = feat @ (W1h + W1l), fp32 accum ----------------------
    float acc[4][4];
#pragma unroll
    for (int nt = 0; nt < 4; ++nt)
#pragma unroll
      for (int j = 0; j < 4; ++j) acc[nt][j] = 0.0f;
#pragma unroll
    for (int k = 0; k < 4; ++k)
#pragma unroll
      for (int nt = 0; nt < 4; ++nt) mma16816(acc[nt], A[k], bhf[k][nt]);
#pragma unroll
    for (int k = 0; k < 4; ++k)
#pragma unroll
      for (int nt = 0; nt < 4; ++nt) mma16816(acc[nt], A[k], blf[k][nt]);

    // ---- layer 2: logits = relu(h) @ W2 + b2 via second mma ---------------
    float o[4] = {bq0, bq1, bq0, bq1};
#pragma unroll
    for (int ks = 0; ks < 2; ++ks) {
      const int ntA = 2 * ks, ntB = 2 * ks + 1;
      float r0 = fmaxf(acc[ntA][0], 0.f), r1 = fmaxf(acc[ntA][1], 0.f);
      float r2 = fmaxf(acc[ntA][2], 0.f), r3 = fmaxf(acc[ntA][3], 0.f);
      float r4 = fmaxf(acc[ntB][0], 0.f), r5 = fmaxf(acc[ntB][1], 0.f);
      float r6 = fmaxf(acc[ntB][2], 0.f), r7 = fmaxf(acc[ntB][3], 0.f);
      uint32_t ah[4], al[4];
      ah[0] = pack_bf16(r0, r1);
      ah[1] = pack_bf16(r2, r3);
      ah[2] = pack_bf16(r4, r5);
      ah[3] = pack_bf16(r6, r7);
      al[0] = resid_pack(ah[0], r0, r1);
      al[1] = resid_pack(ah[1], r2, r3);
      al[2] = resid_pack(ah[2], r4, r5);
      al[3] = resid_pack(ah[3], r6, r7);
      mma16816(o, ah, w2hf[ks]);
      mma16816(o, al, w2hf[ks]);
      mma16816(o, ah, w2lf[ks]);
    }

    // ---- store: out[bb][n][y][x], lane owns n = 2lq,2lq+1; x = x1, x2 -----
    float* op = out + (((size_t)bb * 8 + lq * 2) * 256 + y) * 256;
    op[x1] = o[0];
    op[65536 + x1] = o[1];
    op[x2] = o[2];
    op[65536 + x2] = o[3];
  }
}

extern "C" void kernel_launch(void* const* d_in, const int* in_sizes, int n_in,
                              void* d_out, int out_size) {
  (void)in_sizes;
  (void)n_in;
  (void)out_size;
  const float* z = (const float*)d_in[0];
  const float* W1 = (const float*)d_in[1];
  const float* b1 = (const float*)d_in[2];
  const float* W2 = (const float*)d_in[3];
  const float* b2 = (const float*)d_in[4];
  float* out = (float*)d_out;
  dim3 grid(32, 32);  // 32 row-strips x 32 batches
  lbp_kernel<<<grid, 256>>>(z, W1, b1, W2, b2, out);
}

// round 3
// speedup vs baseline: 1.3333x; 1.3333x over previous
#include <cuda_runtime.h>
#include <cuda_bf16.h>
#include <cstdint>

// ---------------------------------------------------------------------------
// LocalBitPredictor: per-pixel 2-layer MLP over 71 binary 3x3-neighborhood
// bits of an 8-channel binary image.
// Layer 1: int8 IMMA m16n8k32, K=64 (k = pidx*8 + c; k=63 is the bias lane).
//   W1 quantized w ~= 2^-17 * (128*a + b), a,b in s8 (error <= 2^-18 abs).
//   Both halves accumulate into ONE s32 chain: pass1 A-bytes = feat*128 (u8),
//   pass2 A-bytes = feat.
// Layer 2: bf16 mma m16n8k16 on relu(h), A hi/lo split (proven exact-ish).
// ---------------------------------------------------------------------------

#define ZROW 264    // packed z row stride (256 + halo + pad)
#define BQSTRIDE 68 // int8 weight row stride (64 + 4 pad, conflict-free)
#define W2STRIDE 72 // W2 smem row stride (32 bf16 = 64B + 8 pad)

static __device__ __forceinline__ void imma16832(int* c, const uint32_t* a,
                                                 const uint32_t* b) {
  asm volatile(
      "mma.sync.aligned.m16n8k32.row.col.s32.u8.s8.s32 "
      "{%0,%1,%2,%3}, {%4,%5,%6,%7}, {%8,%9}, {%0,%1,%2,%3};"
      : "+r"(c[0]), "+r"(c[1]), "+r"(c[2]), "+r"(c[3])
      : "r"(a[0]), "r"(a[1]), "r"(a[2]), "r"(a[3]), "r"(b[0]), "r"(b[1]));
}

static __device__ __forceinline__ void mma16816(float* c, const uint32_t* a,
                                                const uint32_t* b) {
  asm volatile(
      "mma.sync.aligned.m16n8k16.row.col.f32.bf16.bf16.f32 "
      "{%0,%1,%2,%3}, {%4,%5,%6,%7}, {%8,%9}, {%0,%1,%2,%3};"
      : "+f"(c[0]), "+f"(c[1]), "+f"(c[2]), "+f"(c[3])
      : "r"(a[0]), "r"(a[1]), "r"(a[2]), "r"(a[3]), "r"(b[0]), "r"(b[1]));
}

static __device__ __forceinline__ uint32_t pack_bf16(float lo, float hi) {
  uint32_t r;
  asm("cvt.rn.bf16x2.f32 %0, %1, %2;" : "=r"(r) : "f"(hi), "f"(lo));
  return r;
}

static __device__ __forceinline__ uint32_t resid_pack(uint32_t h, float lo,
                                                      float hi) {
  float hlo = __uint_as_float(h << 16);
  float hhi = __uint_as_float(h & 0xFFFF0000u);
  return pack_bf16(lo - hlo, hi - hhi);
}

__global__ void __launch_bounds__(256, 3)
lbp_kernel(const float* __restrict__ z, const float* __restrict__ W1,
           const float* __restrict__ b1, const float* __restrict__ W2,
           const float* __restrict__ b2, float* __restrict__ out) {
  __shared__ unsigned char Zs[10 * ZROW];
  __shared__ signed char Bqa[32 * BQSTRIDE];
  __shared__ signed char Bqb[32 * BQSTRIDE];
  __shared__ unsigned char W2hs[8 * W2STRIDE];
  __shared__ unsigned char W2ls[8 * W2STRIDE];
  __shared__ float b2s[8];

  const int tid = threadIdx.x;
  const int bb = blockIdx.y;      // batch
  const int y0 = blockIdx.x * 8;  // row-strip base

  // ---- pack z into channel-bit bytes: rows y0-1..y0+8, halo cols zeroed ---
  {
    const int x = tid;  // 256 threads == 256 columns
#pragma unroll
    for (int r = 0; r < 10; ++r) {
      int y = y0 + r - 1;
      unsigned v = 0;
      if (y >= 0 && y < 256) {
        const float* zp = z + (size_t)bb * 8 * 65536 + (size_t)y * 256 + x;
#pragma unroll
        for (int c = 0; c < 8; ++c)
          v |= (zp[(size_t)c * 65536] > 0.5f ? 1u : 0u) << c;
      }
      Zs[r * ZROW + x + 1] = (unsigned char)v;
    }
    if (tid < 10) {
      Zs[tid * ZROW + 0] = 0;
      Zs[tid * ZROW + 257] = 0;
    }
  }

  // ---- quantize layer-1 weights: k = pidx*8 + c, p = pidx<4?pidx:pidx+1 ---
  // k==63 (pidx=7,c=7 -> the sliced-off feature 71) carries b1 instead.
  for (int i = tid; i < 2048; i += 256) {
    int d = i & 31, k = i >> 5;
    float w;
    if (k == 63) {
      w = b1[d];
    } else {
      int pidx = k >> 3, c = k & 7;
      int p = pidx < 4 ? pidx : pidx + 1;
      w = W1[(c * 9 + p) * 32 + d];
    }
    int iw = __float2int_rn(w * 131072.0f);  // w * 2^17
    int a = __float2int_rn(w * 1024.0f);     // high part (x128)
    int b = iw - (a << 7);                   // |b| <= 64
    Bqa[d * BQSTRIDE + k] = (signed char)a;
    Bqb[d * BQSTRIDE + k] = (signed char)b;
  }
  // ---- W2 as [n'][d], hi/lo bf16 split; b2 --------------------------------
  {
    int d = tid >> 3, n = tid & 7;
    float w = W2[d * 8 + n];
    __nv_bfloat16 hi = __float2bfloat16(w);
    float hif = __bfloat162float(hi);
    __nv_bfloat16 lo = __float2bfloat16(w - hif);
    *reinterpret_cast<__nv_bfloat16*>(W2hs + n * W2STRIDE + d * 2) = hi;
    *reinterpret_cast<__nv_bfloat16*>(W2ls + n * W2STRIDE + d * 2) = lo;
    if (tid < 8) b2s[tid] = b2[tid];
  }
  __syncthreads();

  const int lane = tid & 31;
  const int warp = tid >> 5;
  const int lq = lane & 3;   // quad: k-word group / output-n group
  const int lr = lane >> 2;  // row-in-fragment group

  // ---- hoist layer-1 int8 B fragments (2 ksteps x 4 ntiles x 2 passes) ----
  uint32_t bA[2][4][2], bB[2][4][2];
#pragma unroll
  for (int ks = 0; ks < 2; ++ks)
#pragma unroll
    for (int nt = 0; nt < 4; ++nt) {
      const signed char* pa = Bqa + (nt * 8 + lr) * BQSTRIDE;
      const signed char* pb = Bqb + (nt * 8 + lr) * BQSTRIDE;
      bA[ks][nt][0] = *reinterpret_cast<const uint32_t*>(pa + (lq + 8 * ks) * 4);
      bA[ks][nt][1] = *reinterpret_cast<const uint32_t*>(pa + (lq + 4 + 8 * ks) * 4);
      bB[ks][nt][0] = *reinterpret_cast<const uint32_t*>(pb + (lq + 8 * ks) * 4);
      bB[ks][nt][1] = *reinterpret_cast<const uint32_t*>(pb + (lq + 4 + 8 * ks) * 4);
    }
  uint32_t w2hf[2][2], w2lf[2][2];
#pragma unroll
  for (int ks = 0; ks < 2; ++ks) {
    const uint32_t* p = reinterpret_cast<const uint32_t*>(
        W2hs + lr * W2STRIDE + (ks * 16 + lq * 2) * 2);
    const uint32_t* q = reinterpret_cast<const uint32_t*>(
        W2ls + lr * W2STRIDE + (ks * 16 + lq * 2) * 2);
    w2hf[ks][0] = p[0];
    w2hf[ks][1] = p[4];
    w2lf[ks][0] = q[0];
    w2lf[ks][1] = q[4];
  }
  const float bq0 = b2s[lq * 2], bq1 = b2s[lq * 2 + 1];

  // lane's 4 neighbor positions: lq<2 -> pidx {0,2,4,6}, else {1,3,5,7};
  // lq odd -> high nibble (channels 4-7).
  const int base_pidx = (lq >> 1) & 1;
  int oP[4];
#pragma unroll
  for (int j = 0; j < 4; ++j) {
    int pidx = base_pidx + 2 * j;
    int p = pidx < 4 ? pidx : pidx + 1;
    oP[j] = (p / 3) * ZROW + (p % 3);
  }
  const int nsh = (lq & 1) * 4;

  // ---- main loop: each warp does 16 tiles of 16 pixels --------------------
  for (int ti = warp; ti < 128; ti += 8) {
    const int row = ti >> 4;        // 0..7 within strip
    const int xb = (ti & 15) * 16;  // tile x base
    const int y = y0 + row;
    const int x1 = xb + lr, x2 = x1 + 8;

    const unsigned char* zb1 = Zs + row * ZROW + x1;
    const unsigned char* zb2 = Zs + row * ZROW + x2;

    uint32_t sp1[4], sp2[4];
#pragma unroll
    for (int j = 0; j < 4; ++j) {
      uint32_t n1 = (zb1[oP[j]] >> nsh) & 0xFu;
      uint32_t n2 = (zb2[oP[j]] >> nsh) & 0xFu;
      sp1[j] = (n1 * 0x00204081u) & 0x01010101u;
      sp2[j] = (n2 * 0x00204081u) & 0x01010101u;
    }
    if (lq == 3) {  // k=63 bias lane (word 15, byte 3): force A byte to 1
      sp1[3] = (sp1[3] & 0x00FFFFFFu) | 0x01000000u;
      sp2[3] = (sp2[3] & 0x00FFFFFFu) | 0x01000000u;
    }

    // ---- layer 1: single s32 chain; pass1 A=feat*128 (u8), pass2 A=feat ---
    int acc[4][4];
#pragma unroll
    for (int nt = 0; nt < 4; ++nt)
#pragma unroll
      for (int j = 0; j < 4; ++j) acc[nt][j] = 0;
#pragma unroll
    for (int ks = 0; ks < 2; ++ks) {
      uint32_t Ahi[4] = {sp1[2 * ks] << 7, sp2[2 * ks] << 7,
                         sp1[2 * ks + 1] << 7, sp2[2 * ks + 1] << 7};
      uint32_t Alo[4] = {sp1[2 * ks], sp2[2 * ks], sp1[2 * ks + 1],
                         sp2[2 * ks + 1]};
#pragma unroll
      for (int nt = 0; nt < 4; ++nt) imma16832(acc[nt], Ahi, bA[ks][nt]);
#pragma unroll
      for (int nt = 0; nt < 4; ++nt) imma16832(acc[nt], Alo, bB[ks][nt]);
    }

    // ---- layer 2: logits = relu(2^-17 * acc) @ W2 + b2 --------------------
    const float S = 7.62939453125e-6f;  // 2^-17
    float o[4] = {bq0, bq1, bq0, bq1};
#pragma unroll
    for (int ks = 0; ks < 2; ++ks) {
      const int ntA = 2 * ks, ntB = 2 * ks + 1;
      float r0 = fmaxf((float)acc[ntA][0] * S, 0.f);
      float r1 = fmaxf((float)acc[ntA][1] * S, 0.f);
      float r2 = fmaxf((float)acc[ntA][2] * S, 0.f);
      float r3 = fmaxf((float)acc[ntA][3] * S, 0.f);
      float r4 = fmaxf((float)acc[ntB][0] * S, 0.f);
      float r5 = fmaxf((float)acc[ntB][1] * S, 0.f);
      float r6 = fmaxf((float)acc[ntB][2] * S, 0.f);
      float r7 = fmaxf((float)acc[ntB][3] * S, 0.f);
      uint32_t ah[4], al[4];
      ah[0] = pack_bf16(r0, r1);
      ah[1] = pack_bf16(r2, r3);
      ah[2] = pack_bf16(r4, r5);
      ah[3] = pack_bf16(r6, r7);
      al[0] = resid_pack(ah[0], r0, r1);
      al[1] = resid_pack(ah[1], r2, r3);
      al[2] = resid_pack(ah[2], r4, r5);
      al[3] = resid_pack(ah[3], r6, r7);
      mma16816(o, ah, w2hf[ks]);
      mma16816(o, al, w2hf[ks]);
      mma16816(o, ah, w2lf[ks]);
    }

    // ---- store: out[bb][n][y][x], lane owns n = 2lq,2lq+1; x = x1, x2 -----
    float* op = out + (((size_t)bb * 8 + lq * 2) * 256 + y) * 256;
    op[x1] = o[0];
    op[65536 + x1] = o[1];
    op[x2] = o[2];
    op[65536 + x2] = o[3];
  }
}

extern "C" void kernel_launch(void* const* d_in, const int* in_sizes, int n_in,
                              void* d_out, int out_size) {
  (void)in_sizes;
  (void)n_in;
  (void)out_size;
  const float* z = (const float*)d_in[0];
  const float* W1 = (const float*)d_in[1];
  const float* b1 = (const float*)d_in[2];
  const float* W2 = (const float*)d_in[3];
  const float* b2 = (const float*)d_in[4];
  float* out = (float*)d_out;
  dim3 grid(32, 32);  // 32 row-strips x 32 batches
  lbp_kernel<<<grid, 256>>>(z, W1, b1, W2, b2, out);
}

// round 4
// speedup vs baseline: 1.4194x; 1.0645x over previous
#include <cuda_runtime.h>
#include <cuda_bf16.h>
#include <cstdint>

// ---------------------------------------------------------------------------
// LocalBitPredictor: per-pixel 2-layer MLP over 71 binary 3x3-neighborhood
// bits of an 8-channel binary image.
// Layer 1: int8 IMMA m16n8k32, K=64 (k = pidx*8 + c; k=63 is the bias lane).
//   W1 quantized w ~= 2^-17 * (128*a + b), a,b in s8. Single s32 accumulator
//   chain: pass1 A-bytes = feat*128 (u8), pass2 A-bytes = feat.
// Layer 2: bf16 mma m16n8k16 on relu_int(acc), 2^-17 folded into W2,
//   A hi/lo split in registers.
// A-build feeds from PRE-SPREAD nibble words computed once in the prologue.
// ---------------------------------------------------------------------------

#define ZROW 264    // spread-word row stride (256 + halo + pad), in words
#define BQSTRIDE 68 // int8 weight row stride (64 + 4 pad)
#define W2STRIDE 72 // W2 smem row stride (32 bf16 = 64B + 8 pad)

static __device__ __forceinline__ void imma16832(int* c, const uint32_t* a,
                                                 const uint32_t* b) {
  asm volatile(
      "mma.sync.aligned.m16n8k32.row.col.s32.u8.s8.s32 "
      "{%0,%1,%2,%3}, {%4,%5,%6,%7}, {%8,%9}, {%0,%1,%2,%3};"
      : "+r"(c[0]), "+r"(c[1]), "+r"(c[2]), "+r"(c[3])
      : "r"(a[0]), "r"(a[1]), "r"(a[2]), "r"(a[3]), "r"(b[0]), "r"(b[1]));
}

static __device__ __forceinline__ void mma16816(float* c, const uint32_t* a,
                                                const uint32_t* b) {
  asm volatile(
      "mma.sync.aligned.m16n8k16.row.col.f32.bf16.bf16.f32 "
      "{%0,%1,%2,%3}, {%4,%5,%6,%7}, {%8,%9}, {%0,%1,%2,%3};"
      : "+f"(c[0]), "+f"(c[1]), "+f"(c[2]), "+f"(c[3])
      : "r"(a[0]), "r"(a[1]), "r"(a[2]), "r"(a[3]), "r"(b[0]), "r"(b[1]));
}

static __device__ __forceinline__ uint32_t pack_bf16(float lo, float hi) {
  uint32_t r;
  asm("cvt.rn.bf16x2.f32 %0, %1, %2;" : "=r"(r) : "f"(hi), "f"(lo));
  return r;
}

static __device__ __forceinline__ uint32_t resid_pack(uint32_t h, float lo,
                                                      float hi) {
  float hlo = __uint_as_float(h << 16);
  float hhi = __uint_as_float(h & 0xFFFF0000u);
  return pack_bf16(lo - hlo, hi - hhi);
}

__global__ void __launch_bounds__(256, 3)
lbp_kernel(const float* __restrict__ z, const float* __restrict__ W1,
           const float* __restrict__ b1, const float* __restrict__ W2,
           const float* __restrict__ b2, float* __restrict__ out) {
  __shared__ uint32_t ZsLo[10 * ZROW];  // spread lo-nibble (channels 0-3)
  __shared__ uint32_t ZsHi[10 * ZROW];  // spread hi-nibble (channels 4-7)
  __shared__ signed char Bqa[32 * BQSTRIDE];
  __shared__ signed char Bqb[32 * BQSTRIDE];
  __shared__ unsigned char W2hs[8 * W2STRIDE];
  __shared__ unsigned char W2ls[8 * W2STRIDE];
  __shared__ float b2s[8];

  const int tid = threadIdx.x;
  const int bb = blockIdx.y;      // batch
  const int y0 = blockIdx.x * 8;  // row-strip base

  // ---- pack + pre-spread z: rows y0-1..y0+8, halo cols zeroed -------------
  {
    const int x = tid;  // 256 threads == 256 columns
#pragma unroll
    for (int r = 0; r < 10; ++r) {
      int y = y0 + r - 1;
      unsigned v = 0;
      if (y >= 0 && y < 256) {
        const float* zp = z + (size_t)bb * 8 * 65536 + (size_t)y * 256 + x;
#pragma unroll
        for (int c = 0; c < 8; ++c)
          v |= (zp[(size_t)c * 65536] > 0.5f ? 1u : 0u) << c;
      }
      ZsLo[r * ZROW + x + 1] = ((v & 0xFu) * 0x00204081u) & 0x01010101u;
      ZsHi[r * ZROW + x + 1] = ((v >> 4) * 0x00204081u) & 0x01010101u;
    }
    if (tid < 10) {
      ZsLo[tid * ZROW + 0] = 0;
      ZsLo[tid * ZROW + 257] = 0;
      ZsHi[tid * ZROW + 0] = 0;
      ZsHi[tid * ZROW + 257] = 0;
    }
  }

  // ---- quantize layer-1 weights: k = pidx*8 + c, p = pidx<4?pidx:pidx+1 ---
  // k==63 carries b1 (bias lane).
  for (int i = tid; i < 2048; i += 256) {
    int d = i & 31, k = i >> 5;
    float w;
    if (k == 63) {
      w = b1[d];
    } else {
      int pidx = k >> 3, c = k & 7;
      int p = pidx < 4 ? pidx : pidx + 1;
      w = W1[(c * 9 + p) * 32 + d];
    }
    int iw = __float2int_rn(w * 131072.0f);  // w * 2^17
    int a = __float2int_rn(w * 1024.0f);     // high part (x128)
    int b = iw - (a << 7);                   // |b| <= 64
    Bqa[d * BQSTRIDE + k] = (signed char)a;
    Bqb[d * BQSTRIDE + k] = (signed char)b;
  }
  // ---- W2 (pre-scaled by 2^-17) as [n'][d], hi/lo bf16 split; b2 ----------
  {
    int d = tid >> 3, n = tid & 7;
    float w = W2[d * 8 + n] * 7.62939453125e-6f;  // fold 2^-17 dequant scale
    __nv_bfloat16 hi = __float2bfloat16(w);
    float hif = __bfloat162float(hi);
    __nv_bfloat16 lo = __float2bfloat16(w - hif);
    *reinterpret_cast<__nv_bfloat16*>(W2hs + n * W2STRIDE + d * 2) = hi;
    *reinterpret_cast<__nv_bfloat16*>(W2ls + n * W2STRIDE + d * 2) = lo;
    if (tid < 8) b2s[tid] = b2[tid];
  }
  __syncthreads();

  const int lane = tid & 31;
  const int warp = tid >> 5;
  const int lq = lane & 3;   // quad: k-word group / output-n group
  const int lr = lane >> 2;  // row-in-fragment group

  // ---- hoist layer-1 int8 B fragments -------------------------------------
  uint32_t bA[2][4][2], bB[2][4][2];
#pragma unroll
  for (int ks = 0; ks < 2; ++ks)
#pragma unroll
    for (int nt = 0; nt < 4; ++nt) {
      const signed char* pa = Bqa + (nt * 8 + lr) * BQSTRIDE;
      const signed char* pb = Bqb + (nt * 8 + lr) * BQSTRIDE;
      bA[ks][nt][0] = *reinterpret_cast<const uint32_t*>(pa + (lq + 8 * ks) * 4);
      bA[ks][nt][1] = *reinterpret_cast<const uint32_t*>(pa + (lq + 4 + 8 * ks) * 4);
      bB[ks][nt][0] = *reinterpret_cast<const uint32_t*>(pb + (lq + 8 * ks) * 4);
      bB[ks][nt][1] = *reinterpret_cast<const uint32_t*>(pb + (lq + 4 + 8 * ks) * 4);
    }
  uint32_t w2hf[2][2], w2lf[2][2];
#pragma unroll
  for (int ks = 0; ks < 2; ++ks) {
    const uint32_t* p = reinterpret_cast<const uint32_t*>(
        W2hs + lr * W2STRIDE + (ks * 16 + lq * 2) * 2);
    const uint32_t* q = reinterpret_cast<const uint32_t*>(
        W2ls + lr * W2STRIDE + (ks * 16 + lq * 2) * 2);
    w2hf[ks][0] = p[0];
    w2hf[ks][1] = p[4];
    w2lf[ks][0] = q[0];
    w2lf[ks][1] = q[4];
  }
  const float bq0 = b2s[lq * 2], bq1 = b2s[lq * 2 + 1];

  // lane's 4 neighbor positions: lq<2 -> pidx {0,2,4,6}, else {1,3,5,7};
  // lq odd -> hi-nibble array (channels 4-7).
  const int base_pidx = (lq >> 1) & 1;
  int oP[4];
#pragma unroll
  for (int j = 0; j < 4; ++j) {
    int pidx = base_pidx + 2 * j;
    int p = pidx < 4 ? pidx : pidx + 1;
    oP[j] = (p / 3) * ZROW + (p % 3);
  }
  const uint32_t* zarr = (lq & 1) ? ZsHi : ZsLo;

  // ---- main loop: each warp does 16 tiles of 16 pixels --------------------
  for (int ti = warp; ti < 128; ti += 8) {
    const int row = ti >> 4;        // 0..7 within strip
    const int xb = (ti & 15) * 16;  // tile x base
    const int y = y0 + row;
    const int x1 = xb + lr, x2 = x1 + 8;

    const uint32_t* zb1 = zarr + row * ZROW + x1;
    const uint32_t* zb2 = zb1 + 8;

    uint32_t sp1[4], sp2[4];
#pragma unroll
    for (int j = 0; j < 4; ++j) {
      sp1[j] = zb1[oP[j]];
      sp2[j] = zb2[oP[j]];
    }
    if (lq == 3) {  // k=63 bias lane (word 15, byte 3): force A byte to 1
      sp1[3] = (sp1[3] & 0x00FFFFFFu) | 0x01000000u;
      sp2[3] = (sp2[3] & 0x00FFFFFFu) | 0x01000000u;
    }

    // ---- layer 1: single s32 chain; pass1 A=feat*128 (u8), pass2 A=feat ---
    int acc[4][4];
#pragma unroll
    for (int nt = 0; nt < 4; ++nt)
#pragma unroll
      for (int j = 0; j < 4; ++j) acc[nt][j] = 0;
#pragma unroll
    for (int ks = 0; ks < 2; ++ks) {
      uint32_t Ahi[4] = {sp1[2 * ks] << 7, sp2[2 * ks] << 7,
                         sp1[2 * ks + 1] << 7, sp2[2 * ks + 1] << 7};
      uint32_t Alo[4] = {sp1[2 * ks], sp2[2 * ks], sp1[2 * ks + 1],
                         sp2[2 * ks + 1]};
#pragma unroll
      for (int nt = 0; nt < 4; ++nt) imma16832(acc[nt], Ahi, bA[ks][nt]);
#pragma unroll
      for (int nt = 0; nt < 4; ++nt) imma16832(acc[nt], Alo, bB[ks][nt]);
    }

    // ---- layer 2: logits = relu_int(acc) @ (2^-17 W2) + b2 ----------------
    float o[4] = {bq0, bq1, bq0, bq1};
#pragma unroll
    for (int ks = 0; ks < 2; ++ks) {
      const int ntA = 2 * ks, ntB = 2 * ks + 1;
      float r0 = (float)max(acc[ntA][0], 0);
      float r1 = (float)max(acc[ntA][1], 0);
      float r2 = (float)max(acc[ntA][2], 0);
      float r3 = (float)max(acc[ntA][3], 0);
      float r4 = (float)max(acc[ntB][0], 0);
      float r5 = (float)max(acc[ntB][1], 0);
      float r6 = (float)max(acc[ntB][2], 0);
      float r7 = (float)max(acc[ntB][3], 0);
      uint32_t ah[4], al[4];
      ah[0] = pack_bf16(r0, r1);
      ah[1] = pack_bf16(r2, r3);
      ah[2] = pack_bf16(r4, r5);
      ah[3] = pack_bf16(r6, r7);
      al[0] = resid_pack(ah[0], r0, r1);
      al[1] = resid_pack(ah[1], r2, r3);
      al[2] = resid_pack(ah[2], r4, r5);
      al[3] = resid_pack(ah[3], r6, r7);
      mma16816(o, ah, w2hf[ks]);
      mma16816(o, al, w2hf[ks]);
      mma16816(o, ah, w2lf[ks]);
    }

    // ---- store: out[bb][n][y][x], lane owns n = 2lq,2lq+1; x = x1, x2 -----
    float* op = out + (((size_t)bb * 8 + lq * 2) * 256 + y) * 256;
    op[x1] = o[0];
    op[65536 + x1] = o[1];
    op[x2] = o[2];
    op[65536 + x2] = o[3];
  }
}

extern "C" void kernel_launch(void* const* d_in, const int* in_sizes, int n_in,
                              void* d_out, int out_size) {
  (void)in_sizes;
  (void)n_in;
  (void)out_size;
  const float* z = (const float*)d_in[0];
  const float* W1 = (const float*)d_in[1];
  const float* b1 = (const float*)d_in[2];
  const float* W2 = (const float*)d_in[3];
  const float* b2 = (const float*)d_in[4];
  float* out = (float*)d_out;
  dim3 grid(32, 32);  // 32 row-strips x 32 batches
  lbp_kernel<<<grid, 256>>>(z, W1, b1, W2, b2, out);
}

// round 7
// speedup vs baseline: 1.5714x; 1.1071x over previous
#include <cuda_runtime.h>
#include <cuda_bf16.h>
#include <cstdint>

// ---------------------------------------------------------------------------
// LocalBitPredictor: per-pixel 2-layer MLP over 71 binary 3x3-neighborhood
// bits of an 8-channel binary image.
// Layer 1: int8 IMMA m16n8k32, K=64 (k = pidx*8 + c; k=63 is the bias lane).
//   W1 quantized w ~= 2^-17 * (128*a + b), a,b in s8. Single s32 accumulator
//   chain: pass1 A-bytes = feat*128 (u8), pass2 A-bytes = feat.
// Layer 2: bf16 mma m16n8k16 on relu_int(acc), 2^-17 folded into W2,
//   A hi/lo split; TWO independent 3-MMA chains (ks=0 / ks=1) merged at end.
// A-build feeds from PRE-SPREAD nibble words computed once in the prologue.
// ---------------------------------------------------------------------------

#define ZROW 264    // spread-word row stride (256 + halo + pad), in words
#define BQSTRIDE 68 // int8 weight row stride (64 + 4 pad)
#define W2STRIDE 72 // W2 smem row stride (32 bf16 = 64B + 8 pad)

static __device__ __forceinline__ void imma16832(int* c, const uint32_t* a,
                                                 const uint32_t* b) {
  asm volatile(
      "mma.sync.aligned.m16n8k32.row.col.s32.u8.s8.s32 "
      "{%0,%1,%2,%3}, {%4,%5,%6,%7}, {%8,%9}, {%0,%1,%2,%3};"
      : "+r"(c[0]), "+r"(c[1]), "+r"(c[2]), "+r"(c[3])
      : "r"(a[0]), "r"(a[1]), "r"(a[2]), "r"(a[3]), "r"(b[0]), "r"(b[1]));
}

static __device__ __forceinline__ void mma16816(float* c, const uint32_t* a,
                                                const uint32_t* b) {
  asm volatile(
      "mma.sync.aligned.m16n8k16.row.col.f32.bf16.bf16.f32 "
      "{%0,%1,%2,%3}, {%4,%5,%6,%7}, {%8,%9}, {%0,%1,%2,%3};"
      : "+f"(c[0]), "+f"(c[1]), "+f"(c[2]), "+f"(c[3])
      : "r"(a[0]), "r"(a[1]), "r"(a[2]), "r"(a[3]), "r"(b[0]), "r"(b[1]));
}

static __device__ __forceinline__ uint32_t pack_bf16(float lo, float hi) {
  uint32_t r;
  asm("cvt.rn.bf16x2.f32 %0, %1, %2;" : "=r"(r) : "f"(hi), "f"(lo));
  return r;
}

static __device__ __forceinline__ uint32_t resid_pack(uint32_t h, float lo,
                                                      float hi) {
  float hlo = __uint_as_float(h << 16);
  float hhi = __uint_as_float(h & 0xFFFF0000u);
  return pack_bf16(lo - hlo, hi - hhi);
}

__global__ void __launch_bounds__(256, 3)
lbp_kernel(const float* __restrict__ z, const float* __restrict__ W1,
           const float* __restrict__ b1, const float* __restrict__ W2,
           const float* __restrict__ b2, float* __restrict__ out) {
  __shared__ uint32_t ZsLo[10 * ZROW];  // spread lo-nibble (channels 0-3)
  __shared__ uint32_t ZsHi[10 * ZROW];  // spread hi-nibble (channels 4-7)
  __shared__ signed char Bqa[32 * BQSTRIDE];
  __shared__ signed char Bqb[32 * BQSTRIDE];
  __shared__ unsigned char W2hs[8 * W2STRIDE];
  __shared__ unsigned char W2ls[8 * W2STRIDE];
  __shared__ float b2s[8];

  const int tid = threadIdx.x;
  const int bb = blockIdx.y;      // batch
  const int y0 = blockIdx.x * 8;  // row-strip base

  // ---- pack + pre-spread z: rows y0-1..y0+8, halo cols zeroed -------------
  // pack via FFMA dot with powers of two (fma pipe, exact: z in {0,1})
  {
    const int x = tid;  // 256 threads == 256 columns
#pragma unroll
    for (int r = 0; r < 10; ++r) {
      int y = y0 + r - 1;
      unsigned v = 0;
      if (y >= 0 && y < 256) {
        const float* zp = z + (size_t)bb * 8 * 65536 + (size_t)y * 256 + x;
        float f = 0.0f;
#pragma unroll
        for (int c = 0; c < 8; ++c)
          f = fmaf(zp[(size_t)c * 65536], (float)(1u << c), f);
        v = (unsigned)f;
      }
      ZsLo[r * ZROW + x + 1] = ((v & 0xFu) * 0x00204081u) & 0x01010101u;
      ZsHi[r * ZROW + x + 1] = ((v >> 4) * 0x00204081u) & 0x01010101u;
    }
    if (tid < 10) {
      ZsLo[tid * ZROW + 0] = 0;
      ZsLo[tid * ZROW + 257] = 0;
      ZsHi[tid * ZROW + 0] = 0;
      ZsHi[tid * ZROW + 257] = 0;
    }
  }

  // ---- quantize layer-1 weights: k = pidx*8 + c, p = pidx<4?pidx:pidx+1 ---
  // k==63 carries b1 (bias lane).
  for (int i = tid; i < 2048; i += 256) {
    int d = i & 31, k = i >> 5;
    float w;
    if (k == 63) {
      w = b1[d];
    } else {
      int pidx = k >> 3, c = k & 7;
      int p = pidx < 4 ? pidx : pidx + 1;
      w = W1[(c * 9 + p) * 32 + d];
    }
    int iw = __float2int_rn(w * 131072.0f);  // w * 2^17
    int a = __float2int_rn(w * 1024.0f);     // high part (x128)
    int b = iw - (a << 7);                   // |b| <= 64
    Bqa[d * BQSTRIDE + k] = (signed char)a;
    Bqb[d * BQSTRIDE + k] = (signed char)b;
  }
  // ---- W2 (pre-scaled by 2^-17) as [n'][d], hi/lo bf16 split; b2 ----------
  {
    int d = tid >> 3, n = tid & 7;
    float w = W2[d * 8 + n] * 7.62939453125e-6f;  // fold 2^-17 dequant scale
    __nv_bfloat16 hi = __float2bfloat16(w);
    float hif = __bfloat162float(hi);
    __nv_bfloat16 lo = __float2bfloat16(w - hif);
    *reinterpret_cast<__nv_bfloat16*>(W2hs + n * W2STRIDE + d * 2) = hi;
    *reinterpret_cast<__nv_bfloat16*>(W2ls + n * W2STRIDE + d * 2) = lo;
    if (tid < 8) b2s[tid] = b2[tid];
  }
  __syncthreads();

  const int lane = tid & 31;
  const int warp = tid >> 5;
  const int lq = lane & 3;   // quad: k-word group / output-n group
  const int lr = lane >> 2;  // row-in-fragment group

  // ---- hoist layer-1 int8 B fragments -------------------------------------
  uint32_t bA[2][4][2], bB[2][4][2];
#pragma unroll
  for (int ks = 0; ks < 2; ++ks)
#pragma unroll
    for (int nt = 0; nt < 4; ++nt) {
      const signed char* pa = Bqa + (nt * 8 + lr) * BQSTRIDE;
      const signed char* pb = Bqb + (nt * 8 + lr) * BQSTRIDE;
      bA[ks][nt][0] = *reinterpret_cast<const uint32_t*>(pa + (lq + 8 * ks) * 4);
      bA[ks][nt][1] = *reinterpret_cast<const uint32_t*>(pa + (lq + 4 + 8 * ks) * 4);
      bB[ks][nt][0] = *reinterpret_cast<const uint32_t*>(pb + (lq + 8 * ks) * 4);
      bB[ks][nt][1] = *reinterpret_cast<const uint32_t*>(pb + (lq + 4 + 8 * ks) * 4);
    }
  uint32_t w2hf[2][2], w2lf[2][2];
#pragma unroll
  for (int ks = 0; ks < 2; ++ks) {
    const uint32_t* p = reinterpret_cast<const uint32_t*>(
        W2hs + lr * W2STRIDE + (ks * 16 + lq * 2) * 2);
    const uint32_t* q = reinterpret_cast<const uint32_t*>(
        W2ls + lr * W2STRIDE + (ks * 16 + lq * 2) * 2);
    w2hf[ks][0] = p[0];
    w2hf[ks][1] = p[4];
    w2lf[ks][0] = q[0];
    w2lf[ks][1] = q[4];
  }
  const float bq0 = b2s[lq * 2], bq1 = b2s[lq * 2 + 1];

  // lane's 4 neighbor positions: lq<2 -> pidx {0,2,4,6}, else {1,3,5,7};
  // lq odd -> hi-nibble array (channels 4-7).
  const int base_pidx = (lq >> 1) & 1;
  int oP[4];
#pragma unroll
  for (int j = 0; j < 4; ++j) {
    int pidx = base_pidx + 2 * j;
    int p = pidx < 4 ? pidx : pidx + 1;
    oP[j] = (p / 3) * ZROW + (p % 3);
  }
  const uint32_t* zarr = (lq & 1) ? ZsHi : ZsLo;

  // ---- main loop: each warp does 16 tiles of 16 pixels --------------------
#pragma unroll 2
  for (int ti = warp; ti < 128; ti += 8) {
    const int row = ti >> 4;        // 0..7 within strip
    const int xb = (ti & 15) * 16;  // tile x base
    const int y = y0 + row;
    const int x1 = xb + lr, x2 = x1 + 8;

    const uint32_t* zb1 = zarr + row * ZROW + x1;
    const uint32_t* zb2 = zb1 + 8;

    uint32_t sp1[4], sp2[4];
#pragma unroll
    for (int j = 0; j < 4; ++j) {
      sp1[j] = zb1[oP[j]];
      sp2[j] = zb2[oP[j]];
    }
    if (lq == 3) {  // k=63 bias lane (word 15, byte 3): force A byte to 1
      sp1[3] = (sp1[3] & 0x00FFFFFFu) | 0x01000000u;
      sp2[3] = (sp2[3] & 0x00FFFFFFu) | 0x01000000u;
    }

    // ---- layer 1: single s32 chain; pass1 A=feat*128 (u8), pass2 A=feat ---
    int acc[4][4];
#pragma unroll
    for (int nt = 0; nt < 4; ++nt)
#pragma unroll
      for (int j = 0; j < 4; ++j) acc[nt][j] = 0;
#pragma unroll
    for (int ks = 0; ks < 2; ++ks) {
      uint32_t Ahi[4] = {sp1[2 * ks] << 7, sp2[2 * ks] << 7,
                         sp1[2 * ks + 1] << 7, sp2[2 * ks + 1] << 7};
      uint32_t Alo[4] = {sp1[2 * ks], sp2[2 * ks], sp1[2 * ks + 1],
                         sp2[2 * ks + 1]};
#pragma unroll
      for (int nt = 0; nt < 4; ++nt) imma16832(acc[nt], Ahi, bA[ks][nt]);
#pragma unroll
      for (int nt = 0; nt < 4; ++nt) imma16832(acc[nt], Alo, bB[ks][nt]);
    }

    // ---- layer 2: two independent 3-MMA chains (ks=0 -> o1, ks=1 -> o2) ---
    float o1[4] = {bq0, bq1, bq0, bq1};
    float o2[4] = {0.f, 0.f, 0.f, 0.f};
    {
      float r0 = (float)max(acc[0][0], 0), r1 = (float)max(acc[0][1], 0);
      float r2 = (float)max(acc[0][2], 0), r3 = (float)max(acc[0][3], 0);
      float r4 = (float)max(acc[1][0], 0), r5 = (float)max(acc[1][1], 0);
      float r6 = (float)max(acc[1][2], 0), r7 = (float)max(acc[1][3], 0);
      uint32_t ah[4], al[4];
      ah[0] = pack_bf16(r0, r1);
      ah[1] = pack_bf16(r2, r3);
      ah[2] = pack_bf16(r4, r5);
      ah[3] = pack_bf16(r6, r7);
      al[0] = resid_pack(ah[0], r0, r1);
      al[1] = resid_pack(ah[1], r2, r3);
      al[2] = resid_pack(ah[2], r4, r5);
      al[3] = resid_pack(ah[3], r6, r7);
      mma16816(o1, ah, w2hf[0]);
      mma16816(o1, al, w2hf[0]);
      mma16816(o1, ah, w2lf[0]);
    }
    {
      float r0 = (float)max(acc[2][0], 0), r1 = (float)max(acc[2][1], 0);
      float r2 = (float)max(acc[2][2], 0), r3 = (float)max(acc[2][3], 0);
      float r4 = (float)max(acc[3][0], 0), r5 = (float)max(acc[3][1], 0);
      float r6 = (float)max(acc[3][2], 0), r7 = (float)max(acc[3][3], 0);
      uint32_t ah[4], al[4];
      ah[0] = pack_bf16(r0, r1);
      ah[1] = pack_bf16(r2, r3);
      ah[2] = pack_bf16(r4, r5);
      ah[3] = pack_bf16(r6, r7);
      al[0] = resid_pack(ah[0], r0, r1);
      al[1] = resid_pack(ah[1], r2, r3);
      al[2] = resid_pack(ah[2], r4, r5);
      al[3] = resid_pack(ah[3], r6, r7);
      mma16816(o2, ah, w2hf[1]);
      mma16816(o2, al, w2hf[1]);
      mma16816(o2, ah, w2lf[1]);
    }

    // ---- store: out[bb][n][y][x], lane owns n = 2lq,2lq+1; x = x1, x2 -----
    float* op = out + (((size_t)bb * 8 + lq * 2) * 256 + y) * 256;
    op[x1] = o1[0] + o2[0];
    op[65536 + x1] = o1[1] + o2[1];
    op[x2] = o1[2] + o2[2];
    op[65536 + x2] = o1[3] + o2[3];
  }
}

extern "C" void kernel_launch(void* const* d_in, const int* in_sizes, int n_in,
                              void* d_out, int out_size) {
  (void)in_sizes;
  (void)n_in;
  (void)out_size;
  const float* z = (const float*)d_in[0];
  const float* W1 = (const float*)d_in[1];
  const float* b1 = (const float*)d_in[2];
  const float* W2 = (const float*)d_in[3];
  const float* b2 = (const float*)d_in[4];
  float* out = (float*)d_out;
  dim3 grid(32, 32);  // 32 row-strips x 32 batches
  lbp_kernel<<<grid, 256>>>(z, W1, b1, W2, b2, out);
}

// round 8
// speedup vs baseline: 1.6296x; 1.0370x over previous
#include <cuda_runtime.h>
#include <cuda_bf16.h>
#include <cstdint>

// ---------------------------------------------------------------------------
// LocalBitPredictor: per-pixel 2-layer MLP over 71 binary 3x3-neighborhood
// bits of an 8-channel binary image.
// Layer 1: int8 IMMA m16n8k32, K=64 (k = pidx*8 + c; k=63 is the bias lane).
//   W1 quantized w ~= 2^-17 * (128*a + b), a,b in s8. Single s32 accumulator
//   chain: pass1 A-bytes = feat*128 (u8), pass2 A-bytes = feat.
//   First IMMA per n-tile uses D != C with a zero C (no acc zero-init MOVs).
// Layer 2: bf16 mma m16n8k16 on relu(I2F(acc)), 2^-17 folded into W2,
//   A hi/lo split; TWO independent 3-MMA chains; o1 seeded with b2 via D!=C.
// A-build feeds from PRE-SPREAD nibble words computed once in the prologue.
// ---------------------------------------------------------------------------

#define ZROW 264    // spread-word row stride (256 + halo + pad), in words
#define BQSTRIDE 68 // int8 weight row stride (64 + 4 pad)
#define W2STRIDE 72 // W2 smem row stride (32 bf16 = 64B + 8 pad)

static __device__ __forceinline__ void imma16832(int* c, const uint32_t* a,
                                                 const uint32_t* b) {
  asm volatile(
      "mma.sync.aligned.m16n8k32.row.col.s32.u8.s8.s32 "
      "{%0,%1,%2,%3}, {%4,%5,%6,%7}, {%8,%9}, {%0,%1,%2,%3};"
      : "+r"(c[0]), "+r"(c[1]), "+r"(c[2]), "+r"(c[3])
      : "r"(a[0]), "r"(a[1]), "r"(a[2]), "r"(a[3]), "r"(b[0]), "r"(b[1]));
}

// D != C form: d = a*b + c, c preserved (lets ptxas use RZ / persistent regs)
static __device__ __forceinline__ void imma16832_dc(int* d, const uint32_t* a,
                                                    const uint32_t* b,
                                                    const int* c) {
  asm volatile(
      "mma.sync.aligned.m16n8k32.row.col.s32.u8.s8.s32 "
      "{%0,%1,%2,%3}, {%4,%5,%6,%7}, {%8,%9}, {%10,%11,%12,%13};"
      : "=r"(d[0]), "=r"(d[1]), "=r"(d[2]), "=r"(d[3])
      : "r"(a[0]), "r"(a[1]), "r"(a[2]), "r"(a[3]), "r"(b[0]), "r"(b[1]),
        "r"(c[0]), "r"(c[1]), "r"(c[2]), "r"(c[3]));
}

static __device__ __forceinline__ void mma16816(float* c, const uint32_t* a,
                                                const uint32_t* b) {
  asm volatile(
      "mma.sync.aligned.m16n8k16.row.col.f32.bf16.bf16.f32 "
      "{%0,%1,%2,%3}, {%4,%5,%6,%7}, {%8,%9}, {%0,%1,%2,%3};"
      : "+f"(c[0]), "+f"(c[1]), "+f"(c[2]), "+f"(c[3])
      : "r"(a[0]), "r"(a[1]), "r"(a[2]), "r"(a[3]), "r"(b[0]), "r"(b[1]));
}

static __device__ __forceinline__ void mma16816_dc(float* d, const uint32_t* a,
                                                   const uint32_t* b,
                                                   const float* c) {
  asm volatile(
      "mma.sync.aligned.m16n8k16.row.col.f32.bf16.bf16.f32 "
      "{%0,%1,%2,%3}, {%4,%5,%6,%7}, {%8,%9}, {%10,%11,%12,%13};"
      : "=f"(d[0]), "=f"(d[1]), "=f"(d[2]), "=f"(d[3])
      : "r"(a[0]), "r"(a[1]), "r"(a[2]), "r"(a[3]), "r"(b[0]), "r"(b[1]),
        "f"(c[0]), "f"(c[1]), "f"(c[2]), "f"(c[3]));
}

static __device__ __forceinline__ uint32_t pack_bf16(float lo, float hi) {
  uint32_t r;
  asm("cvt.rn.bf16x2.f32 %0, %1, %2;" : "=r"(r) : "f"(hi), "f"(lo));
  return r;
}

static __device__ __forceinline__ uint32_t resid_pack(uint32_t h, float lo,
                                                      float hi) {
  float hlo = __uint_as_float(h << 16);
  float hhi = __uint_as_float(h & 0xFFFF0000u);
  return pack_bf16(lo - hlo, hi - hhi);
}

__global__ void __launch_bounds__(256, 3)
lbp_kernel(const float* __restrict__ z, const float* __restrict__ W1,
           const float* __restrict__ b1, const float* __restrict__ W2,
           const float* __restrict__ b2, float* __restrict__ out) {
  __shared__ uint32_t ZsLo[10 * ZROW];  // spread lo-nibble (channels 0-3)
  __shared__ uint32_t ZsHi[10 * ZROW];  // spread hi-nibble (channels 4-7)
  __shared__ signed char Bqa[32 * BQSTRIDE];
  __shared__ signed char Bqb[32 * BQSTRIDE];
  __shared__ unsigned char W2hs[8 * W2STRIDE];
  __shared__ unsigned char W2ls[8 * W2STRIDE];
  __shared__ float b2s[8];

  const int tid = threadIdx.x;
  const int bb = blockIdx.y;      // batch
  const int y0 = blockIdx.x * 8;  // row-strip base

  // ---- pack + pre-spread z: rows y0-1..y0+8, halo cols zeroed -------------
  // pack via FFMA dot with powers of two (fma pipe, exact: z in {0,1})
  {
    const int x = tid;  // 256 threads == 256 columns
#pragma unroll
    for (int r = 0; r < 10; ++r) {
      int y = y0 + r - 1;
      unsigned v = 0;
      if (y >= 0 && y < 256) {
        const float* zp = z + (size_t)bb * 8 * 65536 + (size_t)y * 256 + x;
        float f = 0.0f;
#pragma unroll
        for (int c = 0; c < 8; ++c)
          f = fmaf(zp[(size_t)c * 65536], (float)(1u << c), f);
        v = (unsigned)f;
      }
      ZsLo[r * ZROW + x + 1] = ((v & 0xFu) * 0x00204081u) & 0x01010101u;
      ZsHi[r * ZROW + x + 1] = ((v >> 4) * 0x00204081u) & 0x01010101u;
    }
    if (tid < 10) {
      ZsLo[tid * ZROW + 0] = 0;
      ZsLo[tid * ZROW + 257] = 0;
      ZsHi[tid * ZROW + 0] = 0;
      ZsHi[tid * ZROW + 257] = 0;
    }
  }

  // ---- quantize layer-1 weights: k = pidx*8 + c, p = pidx<4?pidx:pidx+1 ---
  // k==63 carries b1 (bias lane).
  for (int i = tid; i < 2048; i += 256) {
    int d = i & 31, k = i >> 5;
    float w;
    if (k == 63) {
      w = b1[d];
    } else {
      int pidx = k >> 3, c = k & 7;
      int p = pidx < 4 ? pidx : pidx + 1;
      w = W1[(c * 9 + p) * 32 + d];
    }
    int iw = __float2int_rn(w * 131072.0f);  // w * 2^17
    int a = __float2int_rn(w * 1024.0f);     // high part (x128)
    int b = iw - (a << 7);                   // |b| <= 64
    Bqa[d * BQSTRIDE + k] = (signed char)a;
    Bqb[d * BQSTRIDE + k] = (signed char)b;
  }
  // ---- W2 (pre-scaled by 2^-17) as [n'][d], hi/lo bf16 split; b2 ----------
  {
    int d = tid >> 3, n = tid & 7;
    float w = W2[d * 8 + n] * 7.62939453125e-6f;  // fold 2^-17 dequant scale
    __nv_bfloat16 hi = __float2bfloat16(w);
    float hif = __bfloat162float(hi);
    __nv_bfloat16 lo = __float2bfloat16(w - hif);
    *reinterpret_cast<__nv_bfloat16*>(W2hs + n * W2STRIDE + d * 2) = hi;
    *reinterpret_cast<__nv_bfloat16*>(W2ls + n * W2STRIDE + d * 2) = lo;
    if (tid < 8) b2s[tid] = b2[tid];
  }
  __syncthreads();

  const int lane = tid & 31;
  const int warp = tid >> 5;
  const int lq = lane & 3;   // quad: k-word group / output-n group
  const int lr = lane >> 2;  // row-in-fragment group

  // ---- hoist layer-1 int8 B fragments -------------------------------------
  uint32_t bA[2][4][2], bB[2][4][2];
#pragma unroll
  for (int ks = 0; ks < 2; ++ks)
#pragma unroll
    for (int nt = 0; nt < 4; ++nt) {
      const signed char* pa = Bqa + (nt * 8 + lr) * BQSTRIDE;
      const signed char* pb = Bqb + (nt * 8 + lr) * BQSTRIDE;
      bA[ks][nt][0] = *reinterpret_cast<const uint32_t*>(pa + (lq + 8 * ks) * 4);
      bA[ks][nt][1] = *reinterpret_cast<const uint32_t*>(pa + (lq + 4 + 8 * ks) * 4);
      bB[ks][nt][0] = *reinterpret_cast<const uint32_t*>(pb + (lq + 8 * ks) * 4);
      bB[ks][nt][1] = *reinterpret_cast<const uint32_t*>(pb + (lq + 4 + 8 * ks) * 4);
    }
  uint32_t w2hf[2][2], w2lf[2][2];
#pragma unroll
  for (int ks = 0; ks < 2; ++ks) {
    const uint32_t* p = reinterpret_cast<const uint32_t*>(
        W2hs + lr * W2STRIDE + (ks * 16 + lq * 2) * 2);
    const uint32_t* q = reinterpret_cast<const uint32_t*>(
        W2ls + lr * W2STRIDE + (ks * 16 + lq * 2) * 2);
    w2hf[ks][0] = p[0];
    w2hf[ks][1] = p[4];
    w2lf[ks][0] = q[0];
    w2lf[ks][1] = q[4];
  }
  const float cb2[4] = {b2s[lq * 2], b2s[lq * 2 + 1], b2s[lq * 2],
                        b2s[lq * 2 + 1]};
  const float cz4[4] = {0.f, 0.f, 0.f, 0.f};
  const int iz4[4] = {0, 0, 0, 0};

  // lane's 4 neighbor positions: lq<2 -> pidx {0,2,4,6}, else {1,3,5,7};
  // lq odd -> hi-nibble array (channels 4-7).
  const int base_pidx = (lq >> 1) & 1;
  int oP[4];
#pragma unroll
  for (int j = 0; j < 4; ++j) {
    int pidx = base_pidx + 2 * j;
    int p = pidx < 4 ? pidx : pidx + 1;
    oP[j] = (p / 3) * ZROW + (p % 3);
  }
  const uint32_t* zarr = (lq & 1) ? ZsHi : ZsLo;

  // base output pointer for this thread (row y0, pixel column x base handled
  // per tile); lane owns channels n = 2lq, 2lq+1
  float* const obase = out + (((size_t)bb * 8 + lq * 2) * 256 + y0) * 256 + lr;

  // ---- main loop: each warp does 16 tiles of 16 pixels --------------------
#pragma unroll 2
  for (int ti = warp; ti < 128; ti += 8) {
    const int row = ti >> 4;        // 0..7 within strip
    const int xb = (ti & 15) * 16;  // tile x base

    const uint32_t* zb1 = zarr + row * ZROW + xb + lr;
    const uint32_t* zb2 = zb1 + 8;

    uint32_t sp1[4], sp2[4];
#pragma unroll
    for (int j = 0; j < 4; ++j) {
      sp1[j] = zb1[oP[j]];
      sp2[j] = zb2[oP[j]];
    }
    if (lq == 3) {  // k=63 bias lane (word 15, byte 3): force A byte to 1
      sp1[3] = (sp1[3] & 0x00FFFFFFu) | 0x01000000u;
      sp2[3] = (sp2[3] & 0x00FFFFFFu) | 0x01000000u;
    }

    // ---- layer 1: single s32 chain; pass1 A=feat*128 (u8), pass2 A=feat ---
    // first IMMA per nt uses D != C with zero C (no acc-init MOVs)
    int acc[4][4];
    {
      uint32_t Ahi[4] = {sp1[0] << 7, sp2[0] << 7, sp1[1] << 7, sp2[1] << 7};
      uint32_t Alo[4] = {sp1[0], sp2[0], sp1[1], sp2[1]};
#pragma unroll
      for (int nt = 0; nt < 4; ++nt)
        imma16832_dc(acc[nt], Ahi, bA[0][nt], iz4);
#pragma unroll
      for (int nt = 0; nt < 4; ++nt) imma16832(acc[nt], Alo, bB[0][nt]);
    }
    {
      uint32_t Ahi[4] = {sp1[2] << 7, sp2[2] << 7, sp1[3] << 7, sp2[3] << 7};
      uint32_t Alo[4] = {sp1[2], sp2[2], sp1[3], sp2[3]};
#pragma unroll
      for (int nt = 0; nt < 4; ++nt) imma16832(acc[nt], Ahi, bA[1][nt]);
#pragma unroll
      for (int nt = 0; nt < 4; ++nt) imma16832(acc[nt], Alo, bB[1][nt]);
    }

    // ---- layer 2: two independent 3-MMA chains (ks=0 -> o1, ks=1 -> o2) ---
    // relu on the fma pipe: fmaxf(I2F(acc), 0)  (I2F exact, |acc| < 2^24)
    float o1[4], o2[4];
    {
      float r0 = fmaxf(__int2float_rn(acc[0][0]), 0.f);
      float r1 = fmaxf(__int2float_rn(acc[0][1]), 0.f);
      float r2 = fmaxf(__int2float_rn(acc[0][2]), 0.f);
      float r3 = fmaxf(__int2float_rn(acc[0][3]), 0.f);
      float r4 = fmaxf(__int2float_rn(acc[1][0]), 0.f);
      float r5 = fmaxf(__int2float_rn(acc[1][1]), 0.f);
      float r6 = fmaxf(__int2float_rn(acc[1][2]), 0.f);
      float r7 = fmaxf(__int2float_rn(acc[1][3]), 0.f);
      uint32_t ah[4], al[4];
      ah[0] = pack_bf16(r0, r1);
      ah[1] = pack_bf16(r2, r3);
      ah[2] = pack_bf16(r4, r5);
      ah[3] = pack_bf16(r6, r7);
      al[0] = resid_pack(ah[0], r0, r1);
      al[1] = resid_pack(ah[1], r2, r3);
      al[2] = resid_pack(ah[2], r4, r5);
      al[3] = resid_pack(ah[3], r6, r7);
      mma16816_dc(o1, ah, w2hf[0], cb2);  // seeded with b2, no init MOVs
      mma16816(o1, al, w2hf[0]);
      mma16816(o1, ah, w2lf[0]);
    }
    {
      float r0 = fmaxf(__int2float_rn(acc[2][0]), 0.f);
      float r1 = fmaxf(__int2float_rn(acc[2][1]), 0.f);
      float r2 = fmaxf(__int2float_rn(acc[2][2]), 0.f);
      float r3 = fmaxf(__int2float_rn(acc[2][3]), 0.f);
      float r4 = fmaxf(__int2float_rn(acc[3][0]), 0.f);
      float r5 = fmaxf(__int2float_rn(acc[3][1]), 0.f);
      float r6 = fmaxf(__int2float_rn(acc[3][2]), 0.f);
      float r7 = fmaxf(__int2float_rn(acc[3][3]), 0.f);
      uint32_t ah[4], al[4];
      ah[0] = pack_bf16(r0, r1);
      ah[1] = pack_bf16(r2, r3);
      ah[2] = pack_bf16(r4, r5);
      ah[3] = pack_bf16(r6, r7);
      al[0] = resid_pack(ah[0], r0, r1);
      al[1] = resid_pack(ah[1], r2, r3);
      al[2] = resid_pack(ah[2], r4, r5);
      al[3] = resid_pack(ah[3], r6, r7);
      mma16816_dc(o2, ah, w2hf[1], cz4);  // zero C, no init MOVs
      mma16816(o2, al, w2hf[1]);
      mma16816(o2, ah, w2lf[1]);
    }

    // ---- store: out[bb][n][y][x]; o1+o2 merged at store ------------------
    float* op = obase + (size_t)row * 256 + xb;
    op[0] = o1[0] + o2[0];
    op[65536] = o1[1] + o2[1];
    op[8] = o1[2] + o2[2];
    op[65536 + 8] = o1[3] + o2[3];
  }
}

extern "C" void kernel_launch(void* const* d_in, const int* in_sizes, int n_in,
                              void* d_out, int out_size) {
  (void)in_sizes;
  (void)n_in;
  (void)out_size;
  const float* z = (const float*)d_in[0];
  const float* W1 = (const float*)d_in[1];
  const float* b1 = (const float*)d_in[2];
  const float* W2 = (const float*)d_in[3];
  const float* b2 = (const float*)d_in[4];
  float* out = (float*)d_out;
  dim3 grid(32, 32);  // 32 row-strips x 32 batches
  lbp_kernel<<<grid, 256>>>(z, W1, b1, W2, b2, out);
}